// round 7
// baseline (speedup 1.0000x reference)
#include <cuda_runtime.h>
#include <cstdint>

#define N_NODES 50000
#define N_EDGES 800000
#define DIM 128
#define LN_EPS 1e-5f

// ---------------- scratch: __device__ globals, device-side references only --
__device__ int    g_is64;                 // 1 if edge_index arrives as int64
__device__ int    g_deg[N_NODES];
__device__ int    g_rowptr[N_NODES + 1];
__device__ int    g_cursor[N_NODES];
__device__ int    g_colsrc[N_EDGES];
__device__ float4 g_mean4[(size_t)N_NODES * 32];   // 25.6 MB, 16B-aligned
__device__ float4 g_h14[(size_t)N_NODES * 32];     // 25.6 MB, 16B-aligned

// ---------------- dtype probe: int64 indices < 50000 => odd int32 lanes == 0
__global__ void k_probe(const int* __restrict__ ei32) {
    if (threadIdx.x == 0 && blockIdx.x == 0) {
        int allzero = 1;
        for (int k = 0; k < 64; k++)
            if (ei32[2 * k + 1] != 0) { allzero = 0; break; }
        g_is64 = allzero;
    }
}

__device__ __forceinline__ int edge_at(const void* __restrict__ ei, int pos) {
    // pos in [0, 2*N_EDGES): logical element index of the edge_index tensor
    if (g_is64) return (int)((const long long*)ei)[pos];
    return ((const int*)ei)[pos];
}

// ---------------- CSR build ----------------
__global__ void k_zero_deg() {
    int i = blockIdx.x * blockDim.x + threadIdx.x;
    if (i < N_NODES) g_deg[i] = 0;
}

__global__ void k_hist(const void* __restrict__ ei) {
    int e = blockIdx.x * blockDim.x + threadIdx.x;
    if (e < N_EDGES) {
        int d = edge_at(ei, N_EDGES + e);           // dst
        if (d >= 0 && d < N_NODES) atomicAdd(&g_deg[d], 1);
    }
}

// single-block exclusive scan over 50000 degrees (1024 threads, chunk=49)
__global__ __launch_bounds__(1024) void k_scan() {
    __shared__ int smx[1024];
    const int T = 1024;
    const int CH = (N_NODES + T - 1) / T;  // 49
    int t = threadIdx.x;
    int base = t * CH;
    int s = 0;
    for (int i = 0; i < CH; i++) {
        int idx = base + i;
        if (idx < N_NODES) s += g_deg[idx];
    }
    smx[t] = s;
    __syncthreads();
    for (int off = 1; off < T; off <<= 1) {
        int v = (t >= off) ? smx[t - off] : 0;
        __syncthreads();
        smx[t] += v;
        __syncthreads();
    }
    int run = (t == 0) ? 0 : smx[t - 1];
    for (int i = 0; i < CH; i++) {
        int idx = base + i;
        if (idx < N_NODES) {
            g_rowptr[idx] = run;
            g_cursor[idx] = run;
            run += g_deg[idx];
        }
    }
    if (t == T - 1) g_rowptr[N_NODES] = run;
}

__global__ void k_fill(const void* __restrict__ ei) {
    int e = blockIdx.x * blockDim.x + threadIdx.x;
    if (e < N_EDGES) {
        int d = edge_at(ei, N_EDGES + e);           // dst
        if (d >= 0 && d < N_NODES) {
            int s = edge_at(ei, e);                 // src
            if (s < 0) s = 0;
            if (s >= N_NODES) s = N_NODES - 1;
            int pos = atomicAdd(&g_cursor[d], 1);
            g_colsrc[pos] = s;
        }
    }
}

// ---------------- mean aggregation: one warp per node ----------------
// input features = use_ext ? h_ext : g_h14 ; output always g_mean4
__global__ void k_aggregate(const float* __restrict__ h_ext, int use_ext) {
    const float4* __restrict__ hv = use_ext ? (const float4*)h_ext : g_h14;
    int w = (blockIdx.x * blockDim.x + threadIdx.x) >> 5;
    int lane = threadIdx.x & 31;
    if (w >= N_NODES) return;
    int beg = g_rowptr[w];
    int end = g_rowptr[w + 1];
    float4 acc = make_float4(0.f, 0.f, 0.f, 0.f);
    int e = beg;
    for (; e + 4 <= end; e += 4) {
        int s0 = g_colsrc[e + 0];
        int s1 = g_colsrc[e + 1];
        int s2 = g_colsrc[e + 2];
        int s3 = g_colsrc[e + 3];
        float4 v0 = hv[s0 * 32 + lane];
        float4 v1 = hv[s1 * 32 + lane];
        float4 v2 = hv[s2 * 32 + lane];
        float4 v3 = hv[s3 * 32 + lane];
        acc.x += (v0.x + v1.x) + (v2.x + v3.x);
        acc.y += (v0.y + v1.y) + (v2.y + v3.y);
        acc.z += (v0.z + v1.z) + (v2.z + v3.z);
        acc.w += (v0.w + v1.w) + (v2.w + v3.w);
    }
    for (; e < end; e++) {
        int s = g_colsrc[e];
        float4 v = hv[s * 32 + lane];
        acc.x += v.x; acc.y += v.y; acc.z += v.z; acc.w += v.w;
    }
    int cnt = end - beg;
    float inv = 1.f / (float)(cnt > 0 ? cnt : 1);
    float4 r;
    r.x = acc.x * inv; r.y = acc.y * inv; r.z = acc.z * inv; r.w = acc.w * inv;
    g_mean4[(size_t)w * 32 + lane] = r;
}

// ---------------- fused dual-GEMM: C = relu(g_mean@Wl^T + Ah@Wr^T + b) -------
// Ah = ah_ext_flag ? Ah_ext : g_h14 ; C = c_ext_flag ? C_ext : g_h14
// Tile: 128 rows x 128 cols, K=256 in 8 chunks of 32. 256 thr, 8x8 microtile.
__global__ __launch_bounds__(256, 2) void k_gemm(
    const float* __restrict__ Ah_ext, int ah_ext_flag,
    const float* __restrict__ Wl,    // [128,128] row-major (o,k)
    const float* __restrict__ Wr,
    const float* __restrict__ bias,  // [128]
    float* __restrict__ C_ext, int c_ext_flag)
{
    const float* Am = (const float*)g_mean4;
    const float* Ah = ah_ext_flag ? Ah_ext : (const float*)g_h14;
    float* C = c_ext_flag ? C_ext : (float*)g_h14;

    __shared__ float As[32][132];    // As[k][m], +4 pad
    __shared__ float Bs[32][132];    // Bs[k][o]
    int tid = threadIdx.x;
    int tx = tid & 15;        // col group
    int ty = tid >> 4;        // row group
    int r0 = blockIdx.x * 128;

    float acc[8][8];
#pragma unroll
    for (int i = 0; i < 8; i++)
#pragma unroll
        for (int j = 0; j < 8; j++) acc[i][j] = 0.f;

#pragma unroll 1
    for (int kt = 0; kt < 8; kt++) {
        int k0 = kt * 32;
        const float* A = (k0 < 128) ? Am : Ah;
        const float* W = (k0 < 128) ? Wl : Wr;
        int ka = k0 & 127;
        __syncthreads();
#pragma unroll
        for (int i = 0; i < 16; i++) {
            int linear = i * 256 + tid;
            int m = linear >> 5, kk = linear & 31;
            int row = r0 + m;
            float v = (row < N_NODES) ? A[(size_t)row * DIM + ka + kk] : 0.f;
            As[kk][m] = v;
        }
#pragma unroll
        for (int i = 0; i < 16; i++) {
            int linear = i * 256 + tid;
            int o = linear >> 5, kk = linear & 31;
            Bs[kk][o] = W[o * DIM + ka + kk];
        }
        __syncthreads();
#pragma unroll
        for (int k = 0; k < 32; k++) {
            float a[8], b[8];
            *(float4*)&a[0] = *(const float4*)&As[k][ty * 8];
            *(float4*)&a[4] = *(const float4*)&As[k][ty * 8 + 4];
            *(float4*)&b[0] = *(const float4*)&Bs[k][tx * 8];
            *(float4*)&b[4] = *(const float4*)&Bs[k][tx * 8 + 4];
#pragma unroll
            for (int i = 0; i < 8; i++)
#pragma unroll
                for (int j = 0; j < 8; j++)
                    acc[i][j] += a[i] * b[j];
        }
    }

    float bv[8];
    *(float4*)&bv[0] = *(const float4*)&bias[tx * 8];
    *(float4*)&bv[4] = *(const float4*)&bias[tx * 8 + 4];
#pragma unroll
    for (int i = 0; i < 8; i++) {
        int row = r0 + ty * 8 + i;
        if (row < N_NODES) {
            float4 o1, o2;
            o1.x = fmaxf(acc[i][0] + bv[0], 0.f);
            o1.y = fmaxf(acc[i][1] + bv[1], 0.f);
            o1.z = fmaxf(acc[i][2] + bv[2], 0.f);
            o1.w = fmaxf(acc[i][3] + bv[3], 0.f);
            o2.x = fmaxf(acc[i][4] + bv[4], 0.f);
            o2.y = fmaxf(acc[i][5] + bv[5], 0.f);
            o2.z = fmaxf(acc[i][6] + bv[6], 0.f);
            o2.w = fmaxf(acc[i][7] + bv[7], 0.f);
            float* cp = C + (size_t)row * DIM + tx * 8;
            *(float4*)cp = o1;
            *(float4*)(cp + 4) = o2;
        }
    }
}

// ---------------- LayerNorm, warp per row, in-place on external buffer ------
__global__ void k_ln(float* __restrict__ io,
                     const float* __restrict__ w,
                     const float* __restrict__ b) {
    int row = (blockIdx.x * blockDim.x + threadIdx.x) >> 5;
    int lane = threadIdx.x & 31;
    if (row >= N_NODES) return;
    float4 v = ((const float4*)io)[(size_t)row * 32 + lane];
    float s = (v.x + v.y) + (v.z + v.w);
#pragma unroll
    for (int off = 16; off > 0; off >>= 1)
        s += __shfl_xor_sync(0xFFFFFFFFu, s, off);
    float mu = s * (1.f / 128.f);
    float dx = v.x - mu, dy = v.y - mu, dz = v.z - mu, dw = v.w - mu;
    float sq = (dx * dx + dy * dy) + (dz * dz + dw * dw);
#pragma unroll
    for (int off = 16; off > 0; off >>= 1)
        sq += __shfl_xor_sync(0xFFFFFFFFu, sq, off);
    float rs = rsqrtf(sq * (1.f / 128.f) + LN_EPS);
    float4 wv = ((const float4*)w)[lane];
    float4 bv = ((const float4*)b)[lane];
    float4 o;
    o.x = dx * rs * wv.x + bv.x;
    o.y = dy * rs * wv.y + bv.y;
    o.z = dz * rs * wv.z + bv.z;
    o.w = dw * rs * wv.w + bv.w;
    ((float4*)io)[(size_t)row * 32 + lane] = o;
}

// ---------------- launch: ONLY kernel launches, no other CUDA API -----------
extern "C" void kernel_launch(void* const* d_in, const int* in_sizes, int n_in,
                              void* d_out, int out_size) {
    const float* x   = (const float*)d_in[0];
    const void*  ei  = d_in[1];                 // int32 or int64, probed on device
    const float* W1l = (const float*)d_in[2];
    const float* b1l = (const float*)d_in[3];
    const float* W1r = (const float*)d_in[4];
    const float* W2l = (const float*)d_in[5];
    const float* b2l = (const float*)d_in[6];
    const float* W2r = (const float*)d_in[7];
    const float* lnw = (const float*)d_in[8];
    const float* lnb = (const float*)d_in[9];
    float* out = (float*)d_out;

    const int TB = 256;
    int gridN  = (N_NODES + TB - 1) / TB;
    int gridE  = (N_EDGES + TB - 1) / TB;
    int gridWN = (N_NODES * 32 + TB - 1) / TB;   // warp-per-node kernels
    int gridG  = (N_NODES + 127) / 128;

    // dtype probe + CSR build
    k_probe<<<1, 32>>>((const int*)ei);
    k_zero_deg<<<gridN, TB>>>();
    k_hist<<<gridE, TB>>>(ei);
    k_scan<<<1, 1024>>>();
    k_fill<<<gridE, TB>>>(ei);

    // layer 1: aggregate(x) -> g_mean4 ; gemm(g_mean4, x) -> g_h14
    k_aggregate<<<gridWN, TB>>>(x, 1);
    k_gemm<<<gridG, TB>>>(x, 1, W1l, W1r, b1l, out, 0);

    // layer 2: aggregate(g_h14) -> g_mean4 ; gemm(g_mean4, g_h14) -> out
    k_aggregate<<<gridWN, TB>>>(x, 0);
    k_gemm<<<gridG, TB>>>(x, 0, W2l, W2r, b2l, out, 1);

    // layernorm (in place on d_out)
    k_ln<<<gridWN, TB>>>(out, lnw, lnb);
}

// round 8
// speedup vs baseline: 2.2342x; 2.2342x over previous
#include <cuda_runtime.h>
#include <cstdint>

#define N_NODES 50000
#define N_EDGES 800000
#define DIM 128
#define LN_EPS 1e-5f
#define SCAN_B 196          // ceil(50000/256)

// ---------------- scratch: __device__ globals, device-side references only --
__device__ int    g_is64;                 // 1 if edge_index arrives as int64
__device__ int    g_deg[N_NODES];
__device__ int    g_rowptr[N_NODES + 1];
__device__ int    g_cursor[N_NODES];
__device__ int    g_colsrc[N_EDGES];
__device__ int    g_bsum[256];            // per-block degree sums (196 used)
__device__ float4 g_mean4[(size_t)N_NODES * 32];   // 25.6 MB
__device__ float4 g_h14[(size_t)N_NODES * 32];     // 25.6 MB

// ---------------- dtype probe: int64 indices < 50000 => odd int32 lanes == 0
__global__ void k_probe(const int* __restrict__ ei32) {
    if (threadIdx.x == 0 && blockIdx.x == 0) {
        int allzero = 1;
        for (int k = 0; k < 64; k++)
            if (ei32[2 * k + 1] != 0) { allzero = 0; break; }
        g_is64 = allzero;
    }
}

__device__ __forceinline__ int edge_at(const void* __restrict__ ei, int pos) {
    if (g_is64) return (int)((const long long*)ei)[pos];
    return ((const int*)ei)[pos];
}

// ---------------- CSR build ----------------
__global__ void k_zero_deg() {
    int i = blockIdx.x * blockDim.x + threadIdx.x;
    if (i < N_NODES) g_deg[i] = 0;
}

__global__ void k_hist(const void* __restrict__ ei) {
    int e = blockIdx.x * blockDim.x + threadIdx.x;
    if (e < N_EDGES) {
        int d = edge_at(ei, N_EDGES + e);
        if (d >= 0 && d < N_NODES) atomicAdd(&g_deg[d], 1);
    }
}

// 3-phase multi-block scan (replaces the 84us single-block scan)
__global__ void k_scan1() {                       // grid=196, block=256
    __shared__ int sm[256];
    int t = threadIdx.x;
    int i = blockIdx.x * 256 + t;
    sm[t] = (i < N_NODES) ? g_deg[i] : 0;
    __syncthreads();
#pragma unroll
    for (int off = 128; off > 0; off >>= 1) {
        if (t < off) sm[t] += sm[t + off];
        __syncthreads();
    }
    if (t == 0) g_bsum[blockIdx.x] = sm[0];
}

__global__ void k_scan2() {                       // grid=1, block=256
    __shared__ int sm[256];
    int t = threadIdx.x;
    int v = (t < SCAN_B) ? g_bsum[t] : 0;
    sm[t] = v;
    __syncthreads();
#pragma unroll
    for (int off = 1; off < 256; off <<= 1) {
        int u = (t >= off) ? sm[t - off] : 0;
        __syncthreads();
        sm[t] += u;
        __syncthreads();
    }
    if (t < SCAN_B) g_bsum[t] = sm[t] - v;        // exclusive block offset
}

__global__ void k_scan3() {                       // grid=196, block=256
    __shared__ int sm[256];
    int t = threadIdx.x;
    int i = blockIdx.x * 256 + t;
    int v = (i < N_NODES) ? g_deg[i] : 0;
    sm[t] = v;
    __syncthreads();
#pragma unroll
    for (int off = 1; off < 256; off <<= 1) {
        int u = (t >= off) ? sm[t - off] : 0;
        __syncthreads();
        sm[t] += u;
        __syncthreads();
    }
    int excl = sm[t] - v + g_bsum[blockIdx.x];
    if (i < N_NODES) { g_rowptr[i] = excl; g_cursor[i] = excl; }
    if (i == N_NODES - 1) g_rowptr[N_NODES] = excl + v;
}

__global__ void k_fill(const void* __restrict__ ei) {
    int e = blockIdx.x * blockDim.x + threadIdx.x;
    if (e < N_EDGES) {
        int d = edge_at(ei, N_EDGES + e);
        if (d >= 0 && d < N_NODES) {
            int s = edge_at(ei, e);
            if (s < 0) s = 0;
            if (s >= N_NODES) s = N_NODES - 1;
            int pos = atomicAdd(&g_cursor[d], 1);
            g_colsrc[pos] = s;
        }
    }
}

// ---------------- mean aggregation: one warp per node ----------------
__global__ void k_aggregate(const float* __restrict__ h_ext, int use_ext) {
    const float4* __restrict__ hv = use_ext ? (const float4*)h_ext : g_h14;
    int w = (blockIdx.x * blockDim.x + threadIdx.x) >> 5;
    int lane = threadIdx.x & 31;
    if (w >= N_NODES) return;
    int beg = g_rowptr[w];
    int end = g_rowptr[w + 1];
    float4 acc = make_float4(0.f, 0.f, 0.f, 0.f);
    int e = beg;
    for (; e + 4 <= end; e += 4) {
        int s0 = g_colsrc[e + 0];
        int s1 = g_colsrc[e + 1];
        int s2 = g_colsrc[e + 2];
        int s3 = g_colsrc[e + 3];
        float4 v0 = hv[s0 * 32 + lane];
        float4 v1 = hv[s1 * 32 + lane];
        float4 v2 = hv[s2 * 32 + lane];
        float4 v3 = hv[s3 * 32 + lane];
        acc.x += (v0.x + v1.x) + (v2.x + v3.x);
        acc.y += (v0.y + v1.y) + (v2.y + v3.y);
        acc.z += (v0.z + v1.z) + (v2.z + v3.z);
        acc.w += (v0.w + v1.w) + (v2.w + v3.w);
    }
    for (; e < end; e++) {
        int s = g_colsrc[e];
        float4 v = hv[s * 32 + lane];
        acc.x += v.x; acc.y += v.y; acc.z += v.z; acc.w += v.w;
    }
    int cnt = end - beg;
    float inv = 1.f / (float)(cnt > 0 ? cnt : 1);
    float4 r;
    r.x = acc.x * inv; r.y = acc.y * inv; r.z = acc.z * inv; r.w = acc.w * inv;
    g_mean4[(size_t)w * 32 + lane] = r;
}

// ---------------- tf32 tensor-core dual-GEMM ----------------
// C = relu([g_mean | Ah] @ [Wl;Wr]^T + b), per-layer K=256.
// Block: 128(M) x 128(N). 8 warps, each 32(M) x 64(N) via m16n8k8 tf32 mma.
__device__ __forceinline__ float to_tf32(float v) {
    uint32_t u;
    asm("cvt.rna.tf32.f32 %0, %1;" : "=r"(u) : "f"(v));
    return __uint_as_float(u);
}

__device__ __forceinline__ void mma_tf32(float c[4], const uint32_t a[4],
                                         const uint32_t b[2]) {
    asm volatile(
        "mma.sync.aligned.m16n8k8.row.col.f32.tf32.tf32.f32 "
        "{%0,%1,%2,%3}, {%4,%5,%6,%7}, {%8,%9}, {%0,%1,%2,%3};\n"
        : "+f"(c[0]), "+f"(c[1]), "+f"(c[2]), "+f"(c[3])
        : "r"(a[0]), "r"(a[1]), "r"(a[2]), "r"(a[3]),
          "r"(b[0]), "r"(b[1]));
}

#define SPAD 36   // smem row stride: bank = (36*g + tg) % 32 = 4g+tg -> conflict-free

__global__ __launch_bounds__(256, 2) void k_gemm(
    const float* __restrict__ Ah_ext, int ah_ext_flag,
    const float* __restrict__ Wl,    // [128,128] row-major (o,k) == B col-major
    const float* __restrict__ Wr,
    const float* __restrict__ bias,  // [128]
    float* __restrict__ C_ext, int c_ext_flag)
{
    const float* Am = (const float*)g_mean4;
    const float* Ah = ah_ext_flag ? Ah_ext : (const float*)g_h14;
    float* C = c_ext_flag ? C_ext : (float*)g_h14;

    __shared__ float As[128][SPAD];   // As[m][k]
    __shared__ float Bs[128][SPAD];   // Bs[n][k]

    int tid = threadIdx.x;
    int wid = tid >> 5, lane = tid & 31;
    int g = lane >> 2, tg = lane & 3;
    int warp_m = (wid >> 1) * 32;
    int warp_n = (wid & 1) * 64;
    int r0 = blockIdx.x * 128;

    float acc[2][8][4];
#pragma unroll
    for (int mt = 0; mt < 2; mt++)
#pragma unroll
        for (int nt = 0; nt < 8; nt++)
#pragma unroll
            for (int q = 0; q < 4; q++) acc[mt][nt][q] = 0.f;

#pragma unroll 1
    for (int kt = 0; kt < 8; kt++) {
        const float* A = (kt < 4) ? Am : Ah;
        const float* W = (kt < 4) ? Wl : Wr;
        int ka = (kt & 3) * 32;
        __syncthreads();
        // fill A tile (coalesced: k fast), converting to tf32 once
#pragma unroll
        for (int i = 0; i < 16; i++) {
            int linear = i * 256 + tid;
            int m = linear >> 5, kk = linear & 31;
            int row = r0 + m;
            float v = (row < N_NODES) ? A[(size_t)row * DIM + ka + kk] : 0.f;
            As[m][kk] = to_tf32(v);
        }
#pragma unroll
        for (int i = 0; i < 16; i++) {
            int linear = i * 256 + tid;
            int n = linear >> 5, kk = linear & 31;
            Bs[n][kk] = to_tf32(W[n * DIM + ka + kk]);
        }
        __syncthreads();

#pragma unroll
        for (int ks = 0; ks < 32; ks += 8) {
            int kc = ks + tg;
            uint32_t afr[2][4];
#pragma unroll
            for (int mt = 0; mt < 2; mt++) {
                int rm = warp_m + mt * 16 + g;
                afr[mt][0] = __float_as_uint(As[rm][kc]);
                afr[mt][1] = __float_as_uint(As[rm + 8][kc]);
                afr[mt][2] = __float_as_uint(As[rm][kc + 4]);
                afr[mt][3] = __float_as_uint(As[rm + 8][kc + 4]);
            }
            uint32_t bfr[8][2];
#pragma unroll
            for (int nt = 0; nt < 8; nt++) {
                int cn = warp_n + nt * 8 + g;
                bfr[nt][0] = __float_as_uint(Bs[cn][kc]);
                bfr[nt][1] = __float_as_uint(Bs[cn][kc + 4]);
            }
#pragma unroll
            for (int mt = 0; mt < 2; mt++)
#pragma unroll
                for (int nt = 0; nt < 8; nt++)
                    mma_tf32(acc[mt][nt], afr[mt], bfr[nt]);
        }
    }

    // epilogue: bias + relu; c0:(g, 2tg) c1:(g, 2tg+1) c2:(g+8, 2tg) c3:(g+8, 2tg+1)
#pragma unroll
    for (int mt = 0; mt < 2; mt++) {
        int row0 = r0 + warp_m + mt * 16 + g;
#pragma unroll
        for (int nt = 0; nt < 8; nt++) {
            int col = warp_n + nt * 8 + tg * 2;
            float b0 = bias[col], b1 = bias[col + 1];
            if (row0 < N_NODES) {
                float2 o;
                o.x = fmaxf(acc[mt][nt][0] + b0, 0.f);
                o.y = fmaxf(acc[mt][nt][1] + b1, 0.f);
                *(float2*)(C + (size_t)row0 * DIM + col) = o;
            }
            if (row0 + 8 < N_NODES) {
                float2 o;
                o.x = fmaxf(acc[mt][nt][2] + b0, 0.f);
                o.y = fmaxf(acc[mt][nt][3] + b1, 0.f);
                *(float2*)(C + (size_t)(row0 + 8) * DIM + col) = o;
            }
        }
    }
}

// ---------------- LayerNorm, warp per row, in-place on external buffer ------
__global__ void k_ln(float* __restrict__ io,
                     const float* __restrict__ w,
                     const float* __restrict__ b) {
    int row = (blockIdx.x * blockDim.x + threadIdx.x) >> 5;
    int lane = threadIdx.x & 31;
    if (row >= N_NODES) return;
    float4 v = ((const float4*)io)[(size_t)row * 32 + lane];
    float s = (v.x + v.y) + (v.z + v.w);
#pragma unroll
    for (int off = 16; off > 0; off >>= 1)
        s += __shfl_xor_sync(0xFFFFFFFFu, s, off);
    float mu = s * (1.f / 128.f);
    float dx = v.x - mu, dy = v.y - mu, dz = v.z - mu, dw = v.w - mu;
    float sq = (dx * dx + dy * dy) + (dz * dz + dw * dw);
#pragma unroll
    for (int off = 16; off > 0; off >>= 1)
        sq += __shfl_xor_sync(0xFFFFFFFFu, sq, off);
    float rs = rsqrtf(sq * (1.f / 128.f) + LN_EPS);
    float4 wv = ((const float4*)w)[lane];
    float4 bv = ((const float4*)b)[lane];
    float4 o;
    o.x = dx * rs * wv.x + bv.x;
    o.y = dy * rs * wv.y + bv.y;
    o.z = dz * rs * wv.z + bv.z;
    o.w = dw * rs * wv.w + bv.w;
    ((float4*)io)[(size_t)row * 32 + lane] = o;
}

// ---------------- launch: ONLY kernel launches, no other CUDA API -----------
extern "C" void kernel_launch(void* const* d_in, const int* in_sizes, int n_in,
                              void* d_out, int out_size) {
    const float* x   = (const float*)d_in[0];
    const void*  ei  = d_in[1];
    const float* W1l = (const float*)d_in[2];
    const float* b1l = (const float*)d_in[3];
    const float* W1r = (const float*)d_in[4];
    const float* W2l = (const float*)d_in[5];
    const float* b2l = (const float*)d_in[6];
    const float* W2r = (const float*)d_in[7];
    const float* lnw = (const float*)d_in[8];
    const float* lnb = (const float*)d_in[9];
    float* out = (float*)d_out;

    const int TB = 256;
    int gridN  = (N_NODES + TB - 1) / TB;        // 196
    int gridE  = (N_EDGES + TB - 1) / TB;
    int gridWN = (N_NODES * 32 + TB - 1) / TB;
    int gridG  = (N_NODES + 127) / 128;          // 391

    // dtype probe + CSR build (multi-block scan)
    k_probe<<<1, 32>>>((const int*)ei);
    k_zero_deg<<<gridN, TB>>>();
    k_hist<<<gridE, TB>>>(ei);
    k_scan1<<<SCAN_B, 256>>>();
    k_scan2<<<1, 256>>>();
    k_scan3<<<SCAN_B, 256>>>();
    k_fill<<<gridE, TB>>>(ei);

    // layer 1: aggregate(x) -> g_mean4 ; gemm(g_mean4, x) -> g_h14
    k_aggregate<<<gridWN, TB>>>(x, 1);
    k_gemm<<<gridG, TB>>>(x, 1, W1l, W1r, b1l, out, 0);

    // layer 2: aggregate(g_h14) -> g_mean4 ; gemm(g_mean4, g_h14) -> out
    k_aggregate<<<gridWN, TB>>>(x, 0);
    k_gemm<<<gridG, TB>>>(x, 0, W2l, W2r, b2l, out, 1);

    // layernorm (in place on d_out)
    k_ln<<<gridWN, TB>>>(out, lnw, lnb);
}

// round 9
// speedup vs baseline: 2.2806x; 1.0207x over previous
#include <cuda_runtime.h>
#include <cuda_fp16.h>
#include <cstdint>

#define N_NODES 50000
#define N_EDGES 800000
#define DIM 128
#define LN_EPS 1e-5f
#define SCAN_B 196          // ceil(50000/256)

// ---------------- scratch: __device__ globals, device-side references only --
__device__ int    g_is64;                 // 1 if edge_index arrives as int64
__device__ int    g_deg[N_NODES];
__device__ int    g_rowptr[N_NODES + 1];
__device__ int    g_cursor[N_NODES];
__device__ int    g_colsrc[N_EDGES];
__device__ int    g_bsum[256];            // per-block degree sums (196 used)
__device__ __half g_P16[(size_t)N_NODES * DIM];    // 12.8 MB (mean branch, pre-agg)
__device__ float  g_Q[(size_t)N_NODES * DIM];      // 25.6 MB (self branch)
__device__ float4 g_h14[(size_t)N_NODES * 32];     // 25.6 MB (layer-1 output)

// ---------------- dtype probe: int64 indices < 50000 => odd int32 lanes == 0
__global__ void k_probe(const int* __restrict__ ei32) {
    if (threadIdx.x == 0 && blockIdx.x == 0) {
        int allzero = 1;
        for (int k = 0; k < 64; k++)
            if (ei32[2 * k + 1] != 0) { allzero = 0; break; }
        g_is64 = allzero;
    }
}

__device__ __forceinline__ int edge_at(const void* __restrict__ ei, int pos) {
    if (g_is64) return (int)((const long long*)ei)[pos];
    return ((const int*)ei)[pos];
}

// ---------------- CSR build ----------------
__global__ void k_zero_deg() {
    int i = blockIdx.x * blockDim.x + threadIdx.x;
    if (i < N_NODES) g_deg[i] = 0;
}

__global__ void k_hist(const void* __restrict__ ei) {
    int e = blockIdx.x * blockDim.x + threadIdx.x;
    if (e < N_EDGES) {
        int d = edge_at(ei, N_EDGES + e);
        if (d >= 0 && d < N_NODES) atomicAdd(&g_deg[d], 1);
    }
}

__global__ void k_scan1() {                       // grid=196, block=256
    __shared__ int sm[256];
    int t = threadIdx.x;
    int i = blockIdx.x * 256 + t;
    sm[t] = (i < N_NODES) ? g_deg[i] : 0;
    __syncthreads();
#pragma unroll
    for (int off = 128; off > 0; off >>= 1) {
        if (t < off) sm[t] += sm[t + off];
        __syncthreads();
    }
    if (t == 0) g_bsum[blockIdx.x] = sm[0];
}

__global__ void k_scan2() {                       // grid=1, block=256
    __shared__ int sm[256];
    int t = threadIdx.x;
    int v = (t < SCAN_B) ? g_bsum[t] : 0;
    sm[t] = v;
    __syncthreads();
#pragma unroll
    for (int off = 1; off < 256; off <<= 1) {
        int u = (t >= off) ? sm[t - off] : 0;
        __syncthreads();
        sm[t] += u;
        __syncthreads();
    }
    if (t < SCAN_B) g_bsum[t] = sm[t] - v;        // exclusive block offset
}

__global__ void k_scan3() {                       // grid=196, block=256
    __shared__ int sm[256];
    int t = threadIdx.x;
    int i = blockIdx.x * 256 + t;
    int v = (i < N_NODES) ? g_deg[i] : 0;
    sm[t] = v;
    __syncthreads();
#pragma unroll
    for (int off = 1; off < 256; off <<= 1) {
        int u = (t >= off) ? sm[t - off] : 0;
        __syncthreads();
        sm[t] += u;
        __syncthreads();
    }
    int excl = sm[t] - v + g_bsum[blockIdx.x];
    if (i < N_NODES) { g_rowptr[i] = excl; g_cursor[i] = excl; }
    if (i == N_NODES - 1) g_rowptr[N_NODES] = excl + v;
}

__global__ void k_fill(const void* __restrict__ ei) {
    int e = blockIdx.x * blockDim.x + threadIdx.x;
    if (e < N_EDGES) {
        int d = edge_at(ei, N_EDGES + e);
        if (d >= 0 && d < N_NODES) {
            int s = edge_at(ei, e);
            if (s < 0) s = 0;
            if (s >= N_NODES) s = N_NODES - 1;
            int pos = atomicAdd(&g_cursor[d], 1);
            g_colsrc[pos] = s;
        }
    }
}

// ---------------- tf32 tensor-core GEMM: out = A @ W^T ----------------
// A [N,128] fp32 (ext or g_h14), W [128,128] row-major (o,k).
// out: fp16 (g_P16) or fp32 (g_Q). No bias (added in combine).
__device__ __forceinline__ float to_tf32(float v) {
    uint32_t u;
    asm("cvt.rna.tf32.f32 %0, %1;" : "=r"(u) : "f"(v));
    return __uint_as_float(u);
}

__device__ __forceinline__ void mma_tf32(float c[4], const uint32_t a[4],
                                         const uint32_t b[2]) {
    asm volatile(
        "mma.sync.aligned.m16n8k8.row.col.f32.tf32.tf32.f32 "
        "{%0,%1,%2,%3}, {%4,%5,%6,%7}, {%8,%9}, {%0,%1,%2,%3};\n"
        : "+f"(c[0]), "+f"(c[1]), "+f"(c[2]), "+f"(c[3])
        : "r"(a[0]), "r"(a[1]), "r"(a[2]), "r"(a[3]),
          "r"(b[0]), "r"(b[1]));
}

#define SPAD 36   // bank = 4g+tg for fragment pattern -> conflict-free

__global__ __launch_bounds__(256, 2) void k_gemm(
    const float* __restrict__ A_ext, int a_ext_flag,
    const float* __restrict__ W,
    int out_fp16)
{
    const float* A = a_ext_flag ? A_ext : (const float*)g_h14;

    __shared__ float As[128][SPAD];   // As[m][k]
    __shared__ float Bs[128][SPAD];   // Bs[n][k]

    int tid = threadIdx.x;
    int wid = tid >> 5, lane = tid & 31;
    int g = lane >> 2, tg = lane & 3;
    int warp_m = (wid >> 1) * 32;
    int warp_n = (wid & 1) * 64;
    int r0 = blockIdx.x * 128;

    float acc[2][8][4];
#pragma unroll
    for (int mt = 0; mt < 2; mt++)
#pragma unroll
        for (int nt = 0; nt < 8; nt++)
#pragma unroll
            for (int q = 0; q < 4; q++) acc[mt][nt][q] = 0.f;

#pragma unroll 1
    for (int kt = 0; kt < 4; kt++) {
        int ka = kt * 32;
        __syncthreads();
#pragma unroll
        for (int i = 0; i < 16; i++) {
            int linear = i * 256 + tid;
            int m = linear >> 5, kk = linear & 31;
            int row = r0 + m;
            float v = (row < N_NODES) ? A[(size_t)row * DIM + ka + kk] : 0.f;
            As[m][kk] = to_tf32(v);
        }
#pragma unroll
        for (int i = 0; i < 16; i++) {
            int linear = i * 256 + tid;
            int n = linear >> 5, kk = linear & 31;
            Bs[n][kk] = to_tf32(W[n * DIM + ka + kk]);
        }
        __syncthreads();

#pragma unroll
        for (int ks = 0; ks < 32; ks += 8) {
            int kc = ks + tg;
            uint32_t afr[2][4];
#pragma unroll
            for (int mt = 0; mt < 2; mt++) {
                int rm = warp_m + mt * 16 + g;
                afr[mt][0] = __float_as_uint(As[rm][kc]);
                afr[mt][1] = __float_as_uint(As[rm + 8][kc]);
                afr[mt][2] = __float_as_uint(As[rm][kc + 4]);
                afr[mt][3] = __float_as_uint(As[rm + 8][kc + 4]);
            }
            uint32_t bfr[8][2];
#pragma unroll
            for (int nt = 0; nt < 8; nt++) {
                int cn = warp_n + nt * 8 + g;
                bfr[nt][0] = __float_as_uint(Bs[cn][kc]);
                bfr[nt][1] = __float_as_uint(Bs[cn][kc + 4]);
            }
#pragma unroll
            for (int mt = 0; mt < 2; mt++)
#pragma unroll
                for (int nt = 0; nt < 8; nt++)
                    mma_tf32(acc[mt][nt], afr[mt], bfr[nt]);
        }
    }

    // epilogue: c0:(g,2tg) c1:(g,2tg+1) c2:(g+8,2tg) c3:(g+8,2tg+1)
#pragma unroll
    for (int mt = 0; mt < 2; mt++) {
        int row0 = r0 + warp_m + mt * 16 + g;
#pragma unroll
        for (int nt = 0; nt < 8; nt++) {
            int col = warp_n + nt * 8 + tg * 2;
            if (out_fp16) {
                if (row0 < N_NODES)
                    *(__half2*)(g_P16 + (size_t)row0 * DIM + col) =
                        __floats2half2_rn(acc[mt][nt][0], acc[mt][nt][1]);
                if (row0 + 8 < N_NODES)
                    *(__half2*)(g_P16 + (size_t)(row0 + 8) * DIM + col) =
                        __floats2half2_rn(acc[mt][nt][2], acc[mt][nt][3]);
            } else {
                if (row0 < N_NODES)
                    *(float2*)(g_Q + (size_t)row0 * DIM + col) =
                        make_float2(acc[mt][nt][0], acc[mt][nt][1]);
                if (row0 + 8 < N_NODES)
                    *(float2*)(g_Q + (size_t)(row0 + 8) * DIM + col) =
                        make_float2(acc[mt][nt][2], acc[mt][nt][3]);
            }
        }
    }
}

// ---------------- combine: out = [LN]( relu( mean_gather(P16) + Q + bias ) ) -
// warp per node; lane owns cols 4*lane..4*lane+3 (8B of P16, 16B of Q).
__global__ void k_combine(const float* __restrict__ bias,
                          const float* __restrict__ lnw,
                          const float* __restrict__ lnb,
                          float* __restrict__ out_ext, int do_ln)
{
    int w = (blockIdx.x * blockDim.x + threadIdx.x) >> 5;
    int lane = threadIdx.x & 31;
    if (w >= N_NODES) return;
    int beg = g_rowptr[w];
    int end = g_rowptr[w + 1];

    float ax = 0.f, ay = 0.f, az = 0.f, aw = 0.f;
    int e = beg;
    for (; e + 4 <= end; e += 4) {
        int s0 = g_colsrc[e + 0];
        int s1 = g_colsrc[e + 1];
        int s2 = g_colsrc[e + 2];
        int s3 = g_colsrc[e + 3];
        uint2 u0 = *(const uint2*)(g_P16 + (size_t)s0 * DIM + lane * 4);
        uint2 u1 = *(const uint2*)(g_P16 + (size_t)s1 * DIM + lane * 4);
        uint2 u2 = *(const uint2*)(g_P16 + (size_t)s2 * DIM + lane * 4);
        uint2 u3 = *(const uint2*)(g_P16 + (size_t)s3 * DIM + lane * 4);
        float2 f0a = __half22float2(*(__half2*)&u0.x), f0b = __half22float2(*(__half2*)&u0.y);
        float2 f1a = __half22float2(*(__half2*)&u1.x), f1b = __half22float2(*(__half2*)&u1.y);
        float2 f2a = __half22float2(*(__half2*)&u2.x), f2b = __half22float2(*(__half2*)&u2.y);
        float2 f3a = __half22float2(*(__half2*)&u3.x), f3b = __half22float2(*(__half2*)&u3.y);
        ax += (f0a.x + f1a.x) + (f2a.x + f3a.x);
        ay += (f0a.y + f1a.y) + (f2a.y + f3a.y);
        az += (f0b.x + f1b.x) + (f2b.x + f3b.x);
        aw += (f0b.y + f1b.y) + (f2b.y + f3b.y);
    }
    for (; e < end; e++) {
        int s = g_colsrc[e];
        uint2 u = *(const uint2*)(g_P16 + (size_t)s * DIM + lane * 4);
        float2 fa = __half22float2(*(__half2*)&u.x), fb = __half22float2(*(__half2*)&u.y);
        ax += fa.x; ay += fa.y; az += fb.x; aw += fb.y;
    }
    int cnt = end - beg;
    float inv = 1.f / (float)(cnt > 0 ? cnt : 1);

    float4 q = *(const float4*)(g_Q + (size_t)w * DIM + lane * 4);
    float4 b4 = ((const float4*)bias)[lane];
    float vx = fmaxf(ax * inv + q.x + b4.x, 0.f);
    float vy = fmaxf(ay * inv + q.y + b4.y, 0.f);
    float vz = fmaxf(az * inv + q.z + b4.z, 0.f);
    float vw = fmaxf(aw * inv + q.w + b4.w, 0.f);

    if (!do_ln) {
        g_h14[(size_t)w * 32 + lane] = make_float4(vx, vy, vz, vw);
        return;
    }
    // fused LayerNorm across the warp (row = 128 values)
    float s = (vx + vy) + (vz + vw);
#pragma unroll
    for (int off = 16; off > 0; off >>= 1)
        s += __shfl_xor_sync(0xFFFFFFFFu, s, off);
    float mu = s * (1.f / 128.f);
    float dx = vx - mu, dy = vy - mu, dz = vz - mu, dw = vw - mu;
    float sq = (dx * dx + dy * dy) + (dz * dz + dw * dw);
#pragma unroll
    for (int off = 16; off > 0; off >>= 1)
        sq += __shfl_xor_sync(0xFFFFFFFFu, sq, off);
    float rs = rsqrtf(sq * (1.f / 128.f) + LN_EPS);
    float4 wv = ((const float4*)lnw)[lane];
    float4 bv = ((const float4*)lnb)[lane];
    float4 o;
    o.x = dx * rs * wv.x + bv.x;
    o.y = dy * rs * wv.y + bv.y;
    o.z = dz * rs * wv.z + bv.z;
    o.w = dw * rs * wv.w + bv.w;
    ((float4*)out_ext)[(size_t)w * 32 + lane] = o;
}

// ---------------- launch: ONLY kernel launches, no other CUDA API -----------
extern "C" void kernel_launch(void* const* d_in, const int* in_sizes, int n_in,
                              void* d_out, int out_size) {
    const float* x   = (const float*)d_in[0];
    const void*  ei  = d_in[1];
    const float* W1l = (const float*)d_in[2];
    const float* b1l = (const float*)d_in[3];
    const float* W1r = (const float*)d_in[4];
    const float* W2l = (const float*)d_in[5];
    const float* b2l = (const float*)d_in[6];
    const float* W2r = (const float*)d_in[7];
    const float* lnw = (const float*)d_in[8];
    const float* lnb = (const float*)d_in[9];
    float* out = (float*)d_out;

    const int TB = 256;
    int gridN  = (N_NODES + TB - 1) / TB;        // 196
    int gridE  = (N_EDGES + TB - 1) / TB;
    int gridWN = (N_NODES * 32 + TB - 1) / TB;
    int gridG  = (N_NODES + 127) / 128;          // 391

    // dtype probe + CSR build
    k_probe<<<1, 32>>>((const int*)ei);
    k_zero_deg<<<gridN, TB>>>();
    k_hist<<<gridE, TB>>>(ei);
    k_scan1<<<SCAN_B, 256>>>();
    k_scan2<<<1, 256>>>();
    k_scan3<<<SCAN_B, 256>>>();
    k_fill<<<gridE, TB>>>(ei);

    // layer 1: P = x@W1l^T (fp16), Q = x@W1r^T (fp32); combine -> g_h14
    k_gemm<<<gridG, TB>>>(x, 1, W1l, 1);
    k_gemm<<<gridG, TB>>>(x, 1, W1r, 0);
    k_combine<<<gridWN, TB>>>(b1l, lnw, lnb, out, 0);

    // layer 2: P = h1@W2l^T (fp16), Q = h1@W2r^T (fp32); combine+LN -> out
    k_gemm<<<gridG, TB>>>(x, 0, W2l, 1);
    k_gemm<<<gridG, TB>>>(x, 0, W2r, 0);
    k_combine<<<gridWN, TB>>>(b2l, lnw, lnb, out, 1);
}